// round 3
// baseline (speedup 1.0000x reference)
#include <cuda_runtime.h>
#include <cstdint>
#include <cmath>

#define NB     4
#define LQ     4096
#define LKV    512
#define DATTN  1024
#define NHEADS 16
#define HDIM   64

// Scratch (device globals: allocation-free rule)
__device__ float g_qh[NB * LQ * DATTN];        // 64 MB
__device__ float g_kv[NB * LKV * 2 * DATTN];   // 16 MB
__device__ float g_attn[NB * LQ * DATTN];      // 64 MB

__device__ __forceinline__ uint32_t f2tf32(float x) {
    uint32_t y;
    asm("cvt.rna.tf32.f32 %0, %1;" : "=r"(y) : "f"(x));
    return y;
}

__device__ __forceinline__ void mma8(float* d, const uint32_t* a, const uint32_t* b) {
    asm volatile(
        "mma.sync.aligned.m16n8k8.row.col.f32.tf32.tf32.f32 "
        "{%0,%1,%2,%3}, {%4,%5,%6,%7}, {%8,%9}, {%0,%1,%2,%3};\n"
        : "+f"(d[0]), "+f"(d[1]), "+f"(d[2]), "+f"(d[3])
        : "r"(a[0]), "r"(a[1]), "r"(a[2]), "r"(a[3]), "r"(b[0]), "r"(b[1]));
}

// C[M,N] = A[M,K] * B[N,K]^T  (fp32 in/out, tf32 compute)
// grid (N/128, M/128), block 256, dyn smem 73728 B.
// Smem layout [row][k] with stride 36 words: fragment loads are bank-conflict-free
// (bank = 4*(lane&3) + (lane>>2), all 32 distinct).
__global__ void __launch_bounds__(256)
gemm_tf32(const float* __restrict__ A, const float* __restrict__ B,
          float* __restrict__ C, int M, int N, int K) {
    extern __shared__ uint32_t smem[];
    const int SA = 36;                       // 32 + 4 pad (words)
    uint32_t* As = smem;                     // [2][128][36]
    uint32_t* Bs = smem + 2 * 128 * SA;      // [2][128][36]

    const int tid  = threadIdx.x;
    const int lane = tid & 31;
    const int wid  = tid >> 5;
    const int wm   = wid & 3;                // M warp: 4 x 32
    const int wn   = wid >> 2;               // N warp: 2 x 64
    const int t    = lane & 3;
    const int g    = lane >> 2;
    const int bm   = blockIdx.y * 128;
    const int bn   = blockIdx.x * 128;

    const float* Ab = A + (size_t)bm * K;
    const float* Bb = B + (size_t)bn * K;

    float acc[2][8][4];
#pragma unroll
    for (int mf = 0; mf < 2; mf++)
#pragma unroll
        for (int nf = 0; nf < 8; nf++)
#pragma unroll
            for (int i = 0; i < 4; i++) acc[mf][nf][i] = 0.f;

    float4 ra[4], rb[4];

    // prologue: load tile 0
#pragma unroll
    for (int p = 0; p < 4; p++) {
        int c = tid + p * 256;
        int row = c >> 3, cc = c & 7;
        ra[p] = *(const float4*)(Ab + (size_t)row * K + cc * 4);
        rb[p] = *(const float4*)(Bb + (size_t)row * K + cc * 4);
    }
    // STS buf 0
#pragma unroll
    for (int p = 0; p < 4; p++) {
        int c = tid + p * 256;
        int row = c >> 3, cc = c & 7;
        uint32_t* da = As + row * SA + cc * 4;
        *(uint4*)da = make_uint4(f2tf32(ra[p].x), f2tf32(ra[p].y), f2tf32(ra[p].z), f2tf32(ra[p].w));
        uint32_t* db = Bs + row * SA + cc * 4;
        *(uint4*)db = make_uint4(f2tf32(rb[p].x), f2tf32(rb[p].y), f2tf32(rb[p].z), f2tf32(rb[p].w));
    }
    __syncthreads();

    const int KT = K >> 5;
    for (int kt = 0; kt < KT; kt++) {
        const int cur = kt & 1;
        const bool pf = (kt + 1 < KT);

        if (pf) {
            const int ko = (kt + 1) << 5;
#pragma unroll
            for (int p = 0; p < 4; p++) {
                int c = tid + p * 256;
                int row = c >> 3, cc = c & 7;
                ra[p] = *(const float4*)(Ab + (size_t)row * K + ko + cc * 4);
                rb[p] = *(const float4*)(Bb + (size_t)row * K + ko + cc * 4);
            }
        }

        const uint32_t* Ac = As + cur * 128 * SA;
        const uint32_t* Bc = Bs + cur * 128 * SA;
#pragma unroll
        for (int kk = 0; kk < 32; kk += 8) {
            uint32_t af[2][4], bf[8][2];
#pragma unroll
            for (int mf = 0; mf < 2; mf++) {
                int r0 = wm * 32 + mf * 16 + g;
                af[mf][0] = Ac[r0 * SA + kk + t];
                af[mf][1] = Ac[(r0 + 8) * SA + kk + t];
                af[mf][2] = Ac[r0 * SA + kk + t + 4];
                af[mf][3] = Ac[(r0 + 8) * SA + kk + t + 4];
            }
#pragma unroll
            for (int nf = 0; nf < 8; nf++) {
                int n0 = wn * 64 + nf * 8 + g;
                bf[nf][0] = Bc[n0 * SA + kk + t];
                bf[nf][1] = Bc[n0 * SA + kk + t + 4];
            }
#pragma unroll
            for (int mf = 0; mf < 2; mf++)
#pragma unroll
                for (int nf = 0; nf < 8; nf++)
                    mma8(acc[mf][nf], af[mf], bf[nf]);
        }

        if (pf) {
            const int nxt = cur ^ 1;
#pragma unroll
            for (int p = 0; p < 4; p++) {
                int c = tid + p * 256;
                int row = c >> 3, cc = c & 7;
                uint32_t* da = As + nxt * 128 * SA + row * SA + cc * 4;
                *(uint4*)da = make_uint4(f2tf32(ra[p].x), f2tf32(ra[p].y), f2tf32(ra[p].z), f2tf32(ra[p].w));
                uint32_t* db = Bs + nxt * 128 * SA + row * SA + cc * 4;
                *(uint4*)db = make_uint4(f2tf32(rb[p].x), f2tf32(rb[p].y), f2tf32(rb[p].z), f2tf32(rb[p].w));
            }
        }
        __syncthreads();
    }

    // epilogue: c0/c1 -> (row g, col 2t), c2/c3 -> (row g+8, col 2t)
#pragma unroll
    for (int mf = 0; mf < 2; mf++) {
#pragma unroll
        for (int nf = 0; nf < 8; nf++) {
            int row = bm + wm * 32 + mf * 16 + g;
            int col = bn + wn * 64 + nf * 8 + t * 2;
            *(float2*)&C[(size_t)row * N + col] = make_float2(acc[mf][nf][0], acc[mf][nf][1]);
            *(float2*)&C[(size_t)(row + 8) * N + col] = make_float2(acc[mf][nf][2], acc[mf][nf][3]);
        }
    }
}

// One warp per (b, q, head). KW=4 lookback window, softmax over 4.
__global__ void __launch_bounds__(256)
attn_kernel(const float* __restrict__ qh, const float* __restrict__ kv,
            const int* __restrict__ seg, float* __restrict__ out) {
    const int gw   = (blockIdx.x * blockDim.x + threadIdx.x) >> 5;
    const int lane = threadIdx.x & 31;
    const int h    = gw & (NHEADS - 1);
    const int qrow = gw >> 4;                // 0 .. NB*LQ-1
    const int b    = qrow >> 12;             // / LQ

    const int s = seg[qrow];

    const float* qp = qh + (size_t)qrow * DATTN + h * HDIM + lane * 2;
    const float2 qv = *(const float2*)qp;

    float  sc[4];
    float2 vv[4];
#pragma unroll
    for (int w = 0; w < 4; w++) {
        int idx = s - w;
        if (idx >= 0) {
            const float* kp = kv + (size_t)(b * LKV + idx) * (2 * DATTN) + h * HDIM + lane * 2;
            float2 kvv = *(const float2*)kp;
            vv[w] = *(const float2*)(kp + DATTN);
            float p = qv.x * kvv.x + qv.y * kvv.y;
#pragma unroll
            for (int o = 16; o > 0; o >>= 1) p += __shfl_xor_sync(0xffffffffu, p, o);
            sc[w] = p * 0.125f;              // HDIM^-0.5
        } else {
            sc[w] = -INFINITY;
            vv[w] = make_float2(0.f, 0.f);
        }
    }

    float m = fmaxf(fmaxf(sc[0], sc[1]), fmaxf(sc[2], sc[3]));
    float e[4], den = 0.f;
#pragma unroll
    for (int w = 0; w < 4; w++) { e[w] = __expf(sc[w] - m); den += e[w]; }
    const float r = 1.f / den;

    float2 o = make_float2(0.f, 0.f);
#pragma unroll
    for (int w = 0; w < 4; w++) {
        o.x += e[w] * r * vv[w].x;
        o.y += e[w] * r * vv[w].y;
    }
    *(float2*)(out + (size_t)qrow * DATTN + h * HDIM + lane * 2) = o;
}

extern "C" void kernel_launch(void* const* d_in, const int* in_sizes, int n_in,
                              void* d_out, int out_size) {
    const float* q      = (const float*)d_in[0];
    const float* kv_src = (const float*)d_in[1];
    const int*   seg    = (const int*)d_in[2];
    const float* Wq     = (const float*)d_in[3];
    const float* Wkv    = (const float*)d_in[4];
    const float* Wo     = (const float*)d_in[5];
    float* out = (float*)d_out;

    float *qh, *kvb, *attn;
    cudaGetSymbolAddress((void**)&qh,   g_qh);
    cudaGetSymbolAddress((void**)&kvb,  g_kv);
    cudaGetSymbolAddress((void**)&attn, g_attn);

    const int SMEM = 2 * 2 * 128 * 36 * 4;   // 73728 B
    cudaFuncSetAttribute(gemm_tf32, cudaFuncAttributeMaxDynamicSharedMemorySize, SMEM);

    dim3 blk(256);
    // qh = q @ Wq^T : (16384,1024) x (1024,1024)
    gemm_tf32<<<dim3(DATTN / 128, (NB * LQ) / 128), blk, SMEM>>>(q, Wq, qh, NB * LQ, DATTN, 1024);
    // kv = kv_src @ Wkv^T : (2048,1024) x (2048,1024)
    gemm_tf32<<<dim3((2 * DATTN) / 128, (NB * LKV) / 128), blk, SMEM>>>(kv_src, Wkv, kvb, NB * LKV, 2 * DATTN, 1024);
    // gathered windowed attention
    attn_kernel<<<(NB * LQ * NHEADS * 32) / 256, 256>>>(qh, kvb, seg, attn);
    // out = attn @ Wo^T
    gemm_tf32<<<dim3(DATTN / 128, (NB * LQ) / 128), blk, SMEM>>>(attn, Wo, out, NB * LQ, DATTN, 1024);
}

// round 4
// speedup vs baseline: 1.0661x; 1.0661x over previous
#include <cuda_runtime.h>
#include <cstdint>
#include <cmath>

#define NB     4
#define LQ     4096
#define LKV    512
#define DATTN  1024
#define NHEADS 16
#define HDIM   64

// Scratch (device globals: allocation-free rule)
__device__ float g_qh[NB * LQ * DATTN];        // 64 MB
__device__ float g_kv[NB * LKV * 2 * DATTN];   // 16 MB
__device__ float g_attn[NB * LQ * DATTN];      // 64 MB

__device__ __forceinline__ uint32_t f2tf32(float x) {
    uint32_t y;
    asm("cvt.rna.tf32.f32 %0, %1;" : "=r"(y) : "f"(x));
    return y;
}

__device__ __forceinline__ void mma8(float* d, const uint32_t* a, const uint32_t* b) {
    asm volatile(
        "mma.sync.aligned.m16n8k8.row.col.f32.tf32.tf32.f32 "
        "{%0,%1,%2,%3}, {%4,%5,%6,%7}, {%8,%9}, {%0,%1,%2,%3};\n"
        : "+f"(d[0]), "+f"(d[1]), "+f"(d[2]), "+f"(d[3])
        : "r"(a[0]), "r"(a[1]), "r"(a[2]), "r"(a[3]), "r"(b[0]), "r"(b[1]));
}

#define SA     36                 // smem row stride in words (32 + 4 pad)
#define STAGES 3
#define TILE_WORDS (128 * SA)     // per matrix per stage
#define SMEM_BYTES (STAGES * 2 * TILE_WORDS * 4)   // 110592

// C[M,N] = A[M,K] * B[N,K]^T  (fp32 in/out, tf32 compute)
// Two independent GEMM "jobs" packed into one grid: blocks [0, split) run job0,
// blocks [split, gridDim.x) run job1 (job1 may be empty: split == gridDim.x).
// block 256 thr, 3-stage cp.async pipeline, 2 CTAs/SM.
__global__ void __launch_bounds__(256, 2)
gemm_tf32(const float* __restrict__ A0, const float* __restrict__ B0, float* __restrict__ C0,
          int M0, int N0,
          const float* __restrict__ A1, const float* __restrict__ B1, float* __restrict__ C1,
          int M1, int N1,
          int K, int split) {
    extern __shared__ float smem[];
    float* As = smem;                          // [STAGES][128][SA]
    float* Bs = smem + STAGES * TILE_WORDS;

    const int tid  = threadIdx.x;
    const int lane = tid & 31;
    const int wid  = tid >> 5;
    const int wm   = wid & 3;                  // M warp: 4 x 32
    const int wn   = wid >> 2;                 // N warp: 2 x 64
    const int t    = lane & 3;
    const int g    = lane >> 2;

    // job dispatch
    const float *A, *B;
    float* C;
    int N, bm, bn;
    if (blockIdx.x < split) {
        A = A0; B = B0; C = C0; N = N0;
        int nbx = N0 >> 7;
        bm = (blockIdx.x / nbx) << 7;
        bn = (blockIdx.x % nbx) << 7;
    } else {
        A = A1; B = B1; C = C1; N = N1;
        int idx = blockIdx.x - split;
        int nbx = N1 >> 7;
        bm = (idx / nbx) << 7;
        bn = (idx % nbx) << 7;
    }

    const float* Ab = A + (size_t)bm * K;
    const float* Bb = B + (size_t)bn * K;

    // per-thread copy coordinates: 4 chunks of 16B per matrix per stage
    const int crow = tid >> 3;        // base row (each p adds 32)
    const int ccol = (tid & 7) * 4;   // word offset within 32-word row

    float acc[2][8][4];
#pragma unroll
    for (int mf = 0; mf < 2; mf++)
#pragma unroll
        for (int nf = 0; nf < 8; nf++)
#pragma unroll
            for (int i = 0; i < 4; i++) acc[mf][nf][i] = 0.f;

#define ISSUE_TILE(st, kt)                                                           \
    do {                                                                             \
        const int _ko = (kt) << 5;                                                   \
        _Pragma("unroll")                                                            \
        for (int p = 0; p < 4; p++) {                                                \
            int row = crow + p * 32;                                                 \
            uint32_t da = (uint32_t)__cvta_generic_to_shared(                        \
                As + (st) * TILE_WORDS + row * SA + ccol);                           \
            const float* ga = Ab + (size_t)row * K + _ko + ccol;                     \
            asm volatile("cp.async.cg.shared.global [%0], [%1], 16;\n"               \
                         :: "r"(da), "l"(ga));                                       \
            uint32_t db = (uint32_t)__cvta_generic_to_shared(                        \
                Bs + (st) * TILE_WORDS + row * SA + ccol);                           \
            const float* gb = Bb + (size_t)row * K + _ko + ccol;                     \
            asm volatile("cp.async.cg.shared.global [%0], [%1], 16;\n"               \
                         :: "r"(db), "l"(gb));                                       \
        }                                                                            \
    } while (0)

    // prologue: stages 0..STAGES-2
    ISSUE_TILE(0, 0);
    asm volatile("cp.async.commit_group;\n");
    ISSUE_TILE(1, 1);
    asm volatile("cp.async.commit_group;\n");

    const int KT = K >> 5;
    int cur = 0;
    for (int kt = 0; kt < KT; kt++) {
        asm volatile("cp.async.wait_group 1;\n");
        __syncthreads();

        if (kt + STAGES - 1 < KT) {
            int nst = cur + STAGES - 1;
            if (nst >= STAGES) nst -= STAGES;
            ISSUE_TILE(nst, kt + STAGES - 1);
        }
        asm volatile("cp.async.commit_group;\n");

        const float* Ac = As + cur * TILE_WORDS;
        const float* Bc = Bs + cur * TILE_WORDS;
#pragma unroll
        for (int kk = 0; kk < 32; kk += 8) {
            uint32_t af[2][4], bf[8][2];
#pragma unroll
            for (int mf = 0; mf < 2; mf++) {
                int r0 = wm * 32 + mf * 16 + g;
                af[mf][0] = f2tf32(Ac[r0 * SA + kk + t]);
                af[mf][1] = f2tf32(Ac[(r0 + 8) * SA + kk + t]);
                af[mf][2] = f2tf32(Ac[r0 * SA + kk + t + 4]);
                af[mf][3] = f2tf32(Ac[(r0 + 8) * SA + kk + t + 4]);
            }
#pragma unroll
            for (int nf = 0; nf < 8; nf++) {
                int n0 = wn * 64 + nf * 8 + g;
                bf[nf][0] = f2tf32(Bc[n0 * SA + kk + t]);
                bf[nf][1] = f2tf32(Bc[n0 * SA + kk + t + 4]);
            }
#pragma unroll
            for (int mf = 0; mf < 2; mf++)
#pragma unroll
                for (int nf = 0; nf < 8; nf++)
                    mma8(acc[mf][nf], af[mf], bf[nf]);
        }

        cur++;
        if (cur >= STAGES) cur = 0;
    }

    // epilogue
#pragma unroll
    for (int mf = 0; mf < 2; mf++) {
#pragma unroll
        for (int nf = 0; nf < 8; nf++) {
            int row = bm + wm * 32 + mf * 16 + g;
            int col = bn + wn * 64 + nf * 8 + t * 2;
            *(float2*)&C[(size_t)row * N + col] = make_float2(acc[mf][nf][0], acc[mf][nf][1]);
            *(float2*)&C[(size_t)(row + 8) * N + col] = make_float2(acc[mf][nf][2], acc[mf][nf][3]);
        }
    }
}

// One warp per (b, q, head). KW=4 lookback window, softmax over 4.
__global__ void __launch_bounds__(256)
attn_kernel(const float* __restrict__ qh, const float* __restrict__ kv,
            const int* __restrict__ seg, float* __restrict__ out) {
    const int gw   = (blockIdx.x * blockDim.x + threadIdx.x) >> 5;
    const int lane = threadIdx.x & 31;
    const int h    = gw & (NHEADS - 1);
    const int qrow = gw >> 4;                // 0 .. NB*LQ-1
    const int b    = qrow >> 12;             // / LQ

    const int s = seg[qrow];

    const float* qp = qh + (size_t)qrow * DATTN + h * HDIM + lane * 2;
    const float2 qv = *(const float2*)qp;

    float  sc[4];
    float2 vv[4];
#pragma unroll
    for (int w = 0; w < 4; w++) {
        int idx = s - w;
        if (idx >= 0) {
            const float* kp = kv + (size_t)(b * LKV + idx) * (2 * DATTN) + h * HDIM + lane * 2;
            float2 kvv = *(const float2*)kp;
            vv[w] = *(const float2*)(kp + DATTN);
            float p = qv.x * kvv.x + qv.y * kvv.y;
#pragma unroll
            for (int o = 16; o > 0; o >>= 1) p += __shfl_xor_sync(0xffffffffu, p, o);
            sc[w] = p * 0.125f;              // HDIM^-0.5
        } else {
            sc[w] = -INFINITY;
            vv[w] = make_float2(0.f, 0.f);
        }
    }

    float m = fmaxf(fmaxf(sc[0], sc[1]), fmaxf(sc[2], sc[3]));
    float e[4], den = 0.f;
#pragma unroll
    for (int w = 0; w < 4; w++) { e[w] = __expf(sc[w] - m); den += e[w]; }
    const float r = 1.f / den;

    float2 o = make_float2(0.f, 0.f);
#pragma unroll
    for (int w = 0; w < 4; w++) {
        o.x += e[w] * r * vv[w].x;
        o.y += e[w] * r * vv[w].y;
    }
    *(float2*)(out + (size_t)qrow * DATTN + h * HDIM + lane * 2) = o;
}

extern "C" void kernel_launch(void* const* d_in, const int* in_sizes, int n_in,
                              void* d_out, int out_size) {
    const float* q      = (const float*)d_in[0];
    const float* kv_src = (const float*)d_in[1];
    const int*   seg    = (const int*)d_in[2];
    const float* Wq     = (const float*)d_in[3];
    const float* Wkv    = (const float*)d_in[4];
    const float* Wo     = (const float*)d_in[5];
    float* out = (float*)d_out;

    float *qh, *kvb, *attn;
    cudaGetSymbolAddress((void**)&qh,   g_qh);
    cudaGetSymbolAddress((void**)&kvb,  g_kv);
    cudaGetSymbolAddress((void**)&attn, g_attn);

    cudaFuncSetAttribute(gemm_tf32, cudaFuncAttributeMaxDynamicSharedMemorySize, SMEM_BYTES);

    const int K = 1024;
    // Job0: qh = q @ Wq^T        (16384 x 1024)  -> 128*8   = 1024 blocks
    // Job1: kv = kv_src @ Wkv^T  (2048  x 2048)  -> 16*16   = 256 blocks
    const int blocks0 = ((NB * LQ) >> 7) * (DATTN >> 7);
    const int blocks1 = ((NB * LKV) >> 7) * ((2 * DATTN) >> 7);
    gemm_tf32<<<blocks0 + blocks1, 256, SMEM_BYTES>>>(
        q, Wq, qh, NB * LQ, DATTN,
        kv_src, Wkv, kvb, NB * LKV, 2 * DATTN,
        K, blocks0);

    // gathered windowed attention
    attn_kernel<<<(NB * LQ * NHEADS * 32) / 256, 256>>>(qh, kvb, seg, attn);

    // out = attn @ Wo^T  (16384 x 1024)
    gemm_tf32<<<blocks0, 256, SMEM_BYTES>>>(
        attn, Wo, out, NB * LQ, DATTN,
        attn, Wo, out, NB * LQ, DATTN,   // unused second job
        K, blocks0);
}

// round 5
// speedup vs baseline: 1.2492x; 1.1718x over previous
#include <cuda_runtime.h>
#include <cstdint>
#include <cmath>

#define NB     4
#define LQ     4096
#define LKV    512
#define DATTN  1024
#define NHEADS 16
#define HDIM   64

// Scratch (device globals: allocation-free rule)
__device__ float g_qh[NB * LQ * DATTN];        // 64 MB
__device__ float g_kv[NB * LKV * 2 * DATTN];   // 16 MB
__device__ float g_attn[NB * LQ * DATTN];      // 64 MB
// tf32-pre-rounded operands
__device__ float g_qr[NB * LQ * 1024];         // 64 MB
__device__ float g_kvsr[NB * LKV * 1024];      // 8 MB
__device__ float g_wq[DATTN * 1024];           // 4 MB
__device__ float g_wkv[2 * DATTN * 1024];      // 8 MB
__device__ float g_wo[1024 * DATTN];           // 4 MB

__device__ __forceinline__ uint32_t f2tf32(float x) {
    uint32_t y;
    asm("cvt.rna.tf32.f32 %0, %1;" : "=r"(y) : "f"(x));
    return y;
}

__device__ __forceinline__ void mma8(float* d, const uint32_t* a, const uint32_t* b) {
    asm volatile(
        "mma.sync.aligned.m16n8k8.row.col.f32.tf32.tf32.f32 "
        "{%0,%1,%2,%3}, {%4,%5,%6,%7}, {%8,%9}, {%0,%1,%2,%3};\n"
        : "+f"(d[0]), "+f"(d[1]), "+f"(d[2]), "+f"(d[3])
        : "r"(a[0]), "r"(a[1]), "r"(a[2]), "r"(a[3]), "r"(b[0]), "r"(b[1]));
}

__device__ __forceinline__ void ldsm_x4(uint32_t& r0, uint32_t& r1, uint32_t& r2,
                                        uint32_t& r3, const float* p) {
    uint32_t addr = (uint32_t)__cvta_generic_to_shared(p);
    asm volatile("ldmatrix.sync.aligned.m8n8.x4.shared.b16 {%0,%1,%2,%3}, [%4];"
                 : "=r"(r0), "=r"(r1), "=r"(r2), "=r"(r3) : "r"(addr));
}

// Elementwise round-to-tf32 (bits kept in fp32 storage)
__global__ void __launch_bounds__(256)
round_tf32(const float4* __restrict__ src, float4* __restrict__ dst, int n4) {
    int i = blockIdx.x * blockDim.x + threadIdx.x;
    if (i < n4) {
        float4 v = src[i];
        float4 o;
        o.x = __uint_as_float(f2tf32(v.x));
        o.y = __uint_as_float(f2tf32(v.y));
        o.z = __uint_as_float(f2tf32(v.z));
        o.w = __uint_as_float(f2tf32(v.w));
        dst[i] = o;
    }
}

#define SA     36                 // smem row stride in words (32 + 4 pad)
#define STAGES 3
#define TILE_WORDS (128 * SA)     // per matrix per stage
#define SMEM_BYTES (STAGES * 2 * TILE_WORDS * 4)   // 110592

// C[M,N] = A[M,K] * B[N,K]^T. A,B already tf32-valued fp32 bits.
// Two jobs packed into one grid: blocks [0,split) = job0, rest = job1.
__global__ void __launch_bounds__(256, 2)
gemm_tf32(const float* __restrict__ A0, const float* __restrict__ B0, float* __restrict__ C0,
          int M0, int N0,
          const float* __restrict__ A1, const float* __restrict__ B1, float* __restrict__ C1,
          int M1, int N1,
          int K, int split) {
    extern __shared__ float smem[];
    float* As = smem;                          // [STAGES][128][SA]
    float* Bs = smem + STAGES * TILE_WORDS;

    const int tid  = threadIdx.x;
    const int lane = tid & 31;
    const int wid  = tid >> 5;
    const int wm   = wid & 3;                  // M warp: 4 x 32
    const int wn   = wid >> 2;                 // N warp: 2 x 64
    const int t    = lane & 3;
    const int g    = lane >> 2;

    // ldmatrix per-lane address components
    const int lane15 = lane & 15;
    const int a_coff = (lane >> 4) << 2;       // 0 or 4
    const int b_roff = (lane & 16) >> 1;       // 0 or 8
    const int b_coff = (lane & 8) >> 1;        // 0 or 4
    const int b_row  = (lane & 7) + b_roff;

    // job dispatch
    const float *A, *B;
    float* C;
    int N, bm, bn;
    if (blockIdx.x < split) {
        A = A0; B = B0; C = C0; N = N0;
        int nbx = N0 >> 7;
        bm = (blockIdx.x / nbx) << 7;
        bn = (blockIdx.x % nbx) << 7;
    } else {
        A = A1; B = B1; C = C1; N = N1;
        int idx = blockIdx.x - split;
        int nbx = N1 >> 7;
        bm = (idx / nbx) << 7;
        bn = (idx % nbx) << 7;
    }

    const float* Ab = A + (size_t)bm * K;
    const float* Bb = B + (size_t)bn * K;

    const int crow = tid >> 3;        // copy row base (each p adds 32)
    const int ccol = (tid & 7) * 4;   // word offset within 32-word k-slab

    float acc[2][8][4];
#pragma unroll
    for (int mf = 0; mf < 2; mf++)
#pragma unroll
        for (int nf = 0; nf < 8; nf++)
#pragma unroll
            for (int i = 0; i < 4; i++) acc[mf][nf][i] = 0.f;

#define ISSUE_TILE(st, kt)                                                           \
    do {                                                                             \
        const int _ko = (kt) << 5;                                                   \
        _Pragma("unroll")                                                            \
        for (int p = 0; p < 4; p++) {                                                \
            int row = crow + p * 32;                                                 \
            uint32_t da = (uint32_t)__cvta_generic_to_shared(                        \
                As + (st) * TILE_WORDS + row * SA + ccol);                           \
            const float* ga = Ab + (size_t)row * K + _ko + ccol;                     \
            asm volatile("cp.async.cg.shared.global [%0], [%1], 16;\n"               \
                         :: "r"(da), "l"(ga));                                       \
            uint32_t db = (uint32_t)__cvta_generic_to_shared(                        \
                Bs + (st) * TILE_WORDS + row * SA + ccol);                           \
            const float* gb = Bb + (size_t)row * K + _ko + ccol;                     \
            asm volatile("cp.async.cg.shared.global [%0], [%1], 16;\n"               \
                         :: "r"(db), "l"(gb));                                       \
        }                                                                            \
    } while (0)

    ISSUE_TILE(0, 0);
    asm volatile("cp.async.commit_group;\n");
    ISSUE_TILE(1, 1);
    asm volatile("cp.async.commit_group;\n");

    const int KT = K >> 5;
    int cur = 0;
    for (int kt = 0; kt < KT; kt++) {
        asm volatile("cp.async.wait_group 1;\n");
        __syncthreads();

        if (kt + STAGES - 1 < KT) {
            int nst = cur + STAGES - 1;
            if (nst >= STAGES) nst -= STAGES;
            ISSUE_TILE(nst, kt + STAGES - 1);
        }
        asm volatile("cp.async.commit_group;\n");

        const float* Ac = As + cur * TILE_WORDS;
        const float* Bc = Bs + cur * TILE_WORDS;
#pragma unroll
        for (int kk = 0; kk < 32; kk += 8) {
            uint32_t af[2][4], bf[8][2];
#pragma unroll
            for (int mf = 0; mf < 2; mf++) {
                const float* p = Ac + (wm * 32 + mf * 16 + lane15) * SA + kk + a_coff;
                ldsm_x4(af[mf][0], af[mf][1], af[mf][2], af[mf][3], p);
            }
#pragma unroll
            for (int nf2 = 0; nf2 < 4; nf2++) {
                const float* p = Bc + (wn * 64 + nf2 * 16 + b_row) * SA + kk + b_coff;
                uint32_t r0, r1, r2, r3;
                ldsm_x4(r0, r1, r2, r3, p);
                bf[2 * nf2][0] = r0; bf[2 * nf2][1] = r1;
                bf[2 * nf2 + 1][0] = r2; bf[2 * nf2 + 1][1] = r3;
            }
#pragma unroll
            for (int mf = 0; mf < 2; mf++)
#pragma unroll
                for (int nf = 0; nf < 8; nf++)
                    mma8(acc[mf][nf], af[mf], bf[nf]);
        }

        cur++;
        if (cur >= STAGES) cur = 0;
    }

    // epilogue
#pragma unroll
    for (int mf = 0; mf < 2; mf++) {
#pragma unroll
        for (int nf = 0; nf < 8; nf++) {
            int row = bm + wm * 32 + mf * 16 + g;
            int col = bn + wn * 64 + nf * 8 + t * 2;
            *(float2*)&C[(size_t)row * N + col] = make_float2(acc[mf][nf][0], acc[mf][nf][1]);
            *(float2*)&C[(size_t)(row + 8) * N + col] = make_float2(acc[mf][nf][2], acc[mf][nf][3]);
        }
    }
}

// One warp per (b, q, head). KW=4 lookback window, softmax over 4.
// Output is pre-rounded to tf32 (it feeds the Wo GEMM's A operand).
__global__ void __launch_bounds__(256)
attn_kernel(const float* __restrict__ qh, const float* __restrict__ kv,
            const int* __restrict__ seg, float* __restrict__ out) {
    const int gw   = (blockIdx.x * blockDim.x + threadIdx.x) >> 5;
    const int lane = threadIdx.x & 31;
    const int h    = gw & (NHEADS - 1);
    const int qrow = gw >> 4;                // 0 .. NB*LQ-1
    const int b    = qrow >> 12;             // / LQ

    const int s = seg[qrow];

    const float* qp = qh + (size_t)qrow * DATTN + h * HDIM + lane * 2;
    const float2 qv = *(const float2*)qp;

    float  sc[4];
    float2 vv[4];
#pragma unroll
    for (int w = 0; w < 4; w++) {
        int idx = s - w;
        if (idx >= 0) {
            const float* kp = kv + (size_t)(b * LKV + idx) * (2 * DATTN) + h * HDIM + lane * 2;
            float2 kvv = *(const float2*)kp;
            vv[w] = *(const float2*)(kp + DATTN);
            float p = qv.x * kvv.x + qv.y * kvv.y;
#pragma unroll
            for (int o = 16; o > 0; o >>= 1) p += __shfl_xor_sync(0xffffffffu, p, o);
            sc[w] = p * 0.125f;              // HDIM^-0.5
        } else {
            sc[w] = -INFINITY;
            vv[w] = make_float2(0.f, 0.f);
        }
    }

    float m = fmaxf(fmaxf(sc[0], sc[1]), fmaxf(sc[2], sc[3]));
    float e[4], den = 0.f;
#pragma unroll
    for (int w = 0; w < 4; w++) { e[w] = __expf(sc[w] - m); den += e[w]; }
    const float r = 1.f / den;

    float2 o = make_float2(0.f, 0.f);
#pragma unroll
    for (int w = 0; w < 4; w++) {
        o.x += e[w] * r * vv[w].x;
        o.y += e[w] * r * vv[w].y;
    }
    float2 ot;
    ot.x = __uint_as_float(f2tf32(o.x));
    ot.y = __uint_as_float(f2tf32(o.y));
    *(float2*)(out + (size_t)qrow * DATTN + h * HDIM + lane * 2) = ot;
}

extern "C" void kernel_launch(void* const* d_in, const int* in_sizes, int n_in,
                              void* d_out, int out_size) {
    const float* q      = (const float*)d_in[0];
    const float* kv_src = (const float*)d_in[1];
    const int*   seg    = (const int*)d_in[2];
    const float* Wq     = (const float*)d_in[3];
    const float* Wkv    = (const float*)d_in[4];
    const float* Wo     = (const float*)d_in[5];
    float* out = (float*)d_out;

    float *qh, *kvb, *attn, *qr, *kvsr, *wq, *wkv, *wo;
    cudaGetSymbolAddress((void**)&qh,   g_qh);
    cudaGetSymbolAddress((void**)&kvb,  g_kv);
    cudaGetSymbolAddress((void**)&attn, g_attn);
    cudaGetSymbolAddress((void**)&qr,   g_qr);
    cudaGetSymbolAddress((void**)&kvsr, g_kvsr);
    cudaGetSymbolAddress((void**)&wq,   g_wq);
    cudaGetSymbolAddress((void**)&wkv,  g_wkv);
    cudaGetSymbolAddress((void**)&wo,   g_wo);

    cudaFuncSetAttribute(gemm_tf32, cudaFuncAttributeMaxDynamicSharedMemorySize, SMEM_BYTES);

    const int K = 1024;

    // pre-round all GEMM operands to tf32
    {
        const int nq   = NB * LQ * 1024 / 4;
        const int nkvs = NB * LKV * 1024 / 4;
        const int nwq  = DATTN * 1024 / 4;
        const int nwkv = 2 * DATTN * 1024 / 4;
        const int nwo  = 1024 * DATTN / 4;
        round_tf32<<<(nq + 255) / 256, 256>>>((const float4*)q, (float4*)qr, nq);
        round_tf32<<<(nkvs + 255) / 256, 256>>>((const float4*)kv_src, (float4*)kvsr, nkvs);
        round_tf32<<<(nwq + 255) / 256, 256>>>((const float4*)Wq, (float4*)wq, nwq);
        round_tf32<<<(nwkv + 255) / 256, 256>>>((const float4*)Wkv, (float4*)wkv, nwkv);
        round_tf32<<<(nwo + 255) / 256, 256>>>((const float4*)Wo, (float4*)wo, nwo);
    }

    // Job0: qh = q @ Wq^T (16384x1024);  Job1: kv = kv_src @ Wkv^T (2048x2048)
    const int blocks0 = ((NB * LQ) >> 7) * (DATTN >> 7);
    const int blocks1 = ((NB * LKV) >> 7) * ((2 * DATTN) >> 7);
    gemm_tf32<<<blocks0 + blocks1, 256, SMEM_BYTES>>>(
        qr, wq, qh, NB * LQ, DATTN,
        kvsr, wkv, kvb, NB * LKV, 2 * DATTN,
        K, blocks0);

    // gathered windowed attention (rounds its own output to tf32)
    attn_kernel<<<(NB * LQ * NHEADS * 32) / 256, 256>>>(qh, kvb, seg, attn);

    // out = attn @ Wo^T (16384 x 1024)
    gemm_tf32<<<blocks0, 256, SMEM_BYTES>>>(
        attn, wo, out, NB * LQ, DATTN,
        attn, wo, out, NB * LQ, DATTN,   // unused second job
        K, blocks0);
}